// round 8
// baseline (speedup 1.0000x reference)
#include <cuda_runtime.h>
#include <cstdint>

#define NN 100000
#define NE 800000
#define SLOPE 0.2f
#define LN_EPS 1e-5f

typedef unsigned long long ull;

// ---------------- scratch (static device globals; no allocation) ----------------
__device__ float  g_z[NN * 128];      // GEMM output z [N,2,64]
__device__ float2 g_el[NN];
__device__ float2 g_er[NN];
__device__ float  g_h1[NN * 64];
__device__ int    g_rowptr[NN + 1];
__device__ int    g_cnt[NN];
__device__ int    g_csrc[NE];
__device__ int    g_blksum[128];

// ---------------- f32x2 packed helpers ----------------
__device__ __forceinline__ void ffma2(ull& d, ull a, ull b) {
    asm("fma.rn.f32x2 %0, %1, %2, %0;" : "+l"(d) : "l"(a), "l"(b));
}
__device__ __forceinline__ ull bcast2(float x) {
    ull r;
    uint32_t u = __float_as_uint(x);
    asm("mov.b64 %0, {%1, %1};" : "=l"(r) : "r"(u));
    return r;
}
__device__ __forceinline__ float2 unpk(ull v) {
    uint32_t lo, hi;
    asm("mov.b64 {%0, %1}, %2;" : "=r"(lo), "=r"(hi) : "l"(v));
    return make_float2(__uint_as_float(lo), __uint_as_float(hi));
}

// ---------------- CSR build ----------------
__global__ void hist_k(const int* __restrict__ dst) {
    int i = blockIdx.x * 256 + threadIdx.x;
    if (i < NE) atomicAdd(&g_cnt[dst[i]], 1);
}

__global__ void scan_blk_k() {
    __shared__ int sh[256];
    int t = threadIdx.x, b = blockIdx.x;
    int base = b * 1024 + t * 4;
    int v0 = 0, v1 = 0, v2 = 0, v3 = 0;
    if (base + 0 < NN) v0 = g_cnt[base + 0];
    if (base + 1 < NN) v1 = g_cnt[base + 1];
    if (base + 2 < NN) v2 = g_cnt[base + 2];
    if (base + 3 < NN) v3 = g_cnt[base + 3];
    int tsum = v0 + v1 + v2 + v3;
    sh[t] = tsum;
    __syncthreads();
    for (int off = 1; off < 256; off <<= 1) {
        int x = 0;
        if (t >= off) x = sh[t - off];
        __syncthreads();
        sh[t] += x;
        __syncthreads();
    }
    int excl = sh[t] - tsum;
    if (t == 255) g_blksum[b] = sh[255];
    if (base + 0 < NN) g_rowptr[base + 0] = excl;
    if (base + 1 < NN) g_rowptr[base + 1] = excl + v0;
    if (base + 2 < NN) g_rowptr[base + 2] = excl + v0 + v1;
    if (base + 3 < NN) g_rowptr[base + 3] = excl + v0 + v1 + v2;
}

__global__ void scan_top_k(int g) {
    __shared__ int sh[128];
    int t = threadIdx.x;
    int v = (t < g) ? g_blksum[t] : 0;
    sh[t] = v;
    __syncthreads();
    for (int off = 1; off < 128; off <<= 1) {
        int x = 0;
        if (t >= off) x = sh[t - off];
        __syncthreads();
        sh[t] += x;
        __syncthreads();
    }
    if (t < g) g_blksum[t] = sh[t] - v;
}

__global__ void scan_add_k() {
    int i = blockIdx.x * 256 + threadIdx.x;
    if (i < NN) g_rowptr[i] += g_blksum[i >> 10];
    if (i == 0) g_rowptr[NN] = NE;
}

__global__ void scatter_k(const int* __restrict__ src, const int* __restrict__ dst) {
    int i = blockIdx.x * 256 + threadIdx.x;
    if (i < NE) {
        int d = dst[i];
        int p = g_rowptr[d] + atomicAdd(&g_cnt[d], 1);
        g_csrc[p] = src[i];
    }
}

// ---------------- GEMM: z = x @ W, 8x8 register tile, f32x2 FMA, 4-kk vector X ----------------
// Block 256 = 16(tx) x 16(ty). Thread: rows {ty*4+j, 64+ty*4+j}, cols {tx*4.., 64+tx*4..}.
// Per 4-kk block: 8 LDS.128 (X rows, broadcast) + 8 LDS.128 (W) -> 128 FFMA2.
template <int FIN>
__global__ void __launch_bounds__(256) gemm_k(const float* __restrict__ x,
                                              const float* __restrict__ W,
                                              const float* __restrict__ al,
                                              const float* __restrict__ ar) {
    extern __shared__ float sm[];
    float* Ws  = sm;                    // 64*128
    float* Xs  = sm + 8192;             // 128*68 (padded stride 68)
    float* Als = sm + 8192 + 128 * 68;  // 128
    float* Ars = Als + 128;             // 128

    const int tid = threadIdx.x;
    if (tid < 128) { Als[tid] = al[tid]; Ars[tid] = ar[tid]; }

    const int tx = tid & 15, ty = tid >> 4;
    const int n0 = blockIdx.x * 128;

    ull acc[8][4];
#pragma unroll
    for (int j = 0; j < 8; j++)
#pragma unroll
        for (int c = 0; c < 4; c++) acc[j][c] = 0ull;

    for (int kt = 0; kt < FIN; kt += 64) {
        // W tile: 64 rows x 128 cols (contiguous)
        const float4* Wg = (const float4*)(W + kt * 128);
        float4* Wsv = (float4*)Ws;
        for (int i = tid; i < 2048; i += 256) Wsv[i] = Wg[i];
        // X tile: 128 rows x 64 cols, stride 68 (k contiguous)
        for (int i = tid; i < 2048; i += 256) {
            int r = i >> 4, c4 = i & 15;
            int gr = n0 + r;
            float4 v = make_float4(0.f, 0.f, 0.f, 0.f);
            if (gr < NN) v = *(const float4*)(x + gr * FIN + kt + c4 * 4);
            *(float4*)(Xs + r * 68 + c4 * 4) = v;
        }
        __syncthreads();
#pragma unroll 2
        for (int k4 = 0; k4 < 64; k4 += 4) {
            float4 xr[8];
#pragma unroll
            for (int j = 0; j < 4; j++) {
                xr[j]     = *(const float4*)(Xs + (ty * 4 + j) * 68 + k4);
                xr[4 + j] = *(const float4*)(Xs + (64 + ty * 4 + j) * 68 + k4);
            }
#pragma unroll
            for (int u = 0; u < 4; u++) {
                ulonglong2 wA = *(const ulonglong2*)(Ws + (k4 + u) * 128 + tx * 4);
                ulonglong2 wB = *(const ulonglong2*)(Ws + (k4 + u) * 128 + 64 + tx * 4);
#pragma unroll
                for (int j = 0; j < 8; j++) {
                    ull bx = bcast2((&xr[j].x)[u]);
                    ffma2(acc[j][0], bx, wA.x);
                    ffma2(acc[j][1], bx, wA.y);
                    ffma2(acc[j][2], bx, wB.x);
                    ffma2(acc[j][3], bx, wB.y);
                }
            }
        }
        __syncthreads();
    }

    // epilogue: per-row el/er partial dots + 16-lane butterfly over tx; store z
    const float* al0 = Als + tx * 4;
    const float* ar0 = Ars + tx * 4;
    const float* al1 = Als + 64 + tx * 4;
    const float* ar1 = Ars + 64 + tx * 4;
#pragma unroll
    for (int j = 0; j < 8; j++) {
        int r = (j < 4) ? (ty * 4 + j) : (64 + ty * 4 + (j - 4));
        float2 c0 = unpk(acc[j][0]), c1 = unpk(acc[j][1]);
        float2 c2 = unpk(acc[j][2]), c3 = unpk(acc[j][3]);
        float el0 = c0.x * al0[0] + c0.y * al0[1] + c1.x * al0[2] + c1.y * al0[3];
        float er0 = c0.x * ar0[0] + c0.y * ar0[1] + c1.x * ar0[2] + c1.y * ar0[3];
        float el1 = c2.x * al1[0] + c2.y * al1[1] + c3.x * al1[2] + c3.y * al1[3];
        float er1 = c2.x * ar1[0] + c2.y * ar1[1] + c3.x * ar1[2] + c3.y * ar1[3];
#pragma unroll
        for (int o = 1; o <= 8; o <<= 1) {
            el0 += __shfl_xor_sync(0xffffffffu, el0, o);
            er0 += __shfl_xor_sync(0xffffffffu, er0, o);
            el1 += __shfl_xor_sync(0xffffffffu, el1, o);
            er1 += __shfl_xor_sync(0xffffffffu, er1, o);
        }
        int gr = n0 + r;
        if (gr < NN) {
            ulonglong2 v0, v1;
            v0.x = acc[j][0]; v0.y = acc[j][1];
            v1.x = acc[j][2]; v1.y = acc[j][3];
            *(ulonglong2*)(g_z + gr * 128 + tx * 4) = v0;
            *(ulonglong2*)(g_z + gr * 128 + 64 + tx * 4) = v1;
            if (tx == 0) {
                g_el[gr] = make_float2(el0, el1);
                g_er[gr] = make_float2(er0, er1);
            }
        }
    }
}

// ---------------- warp-per-node: SINGLE-PASS edge softmax + aggregate (unroll 4) ----------------
__device__ __forceinline__ float lrelu(float v) { return v > 0.f ? v : SLOPE * v; }

template <int LAYER>
__global__ void __launch_bounds__(256) agg_k(const float* __restrict__ bias,
                                             const float* __restrict__ gamma,
                                             const float* __restrict__ beta,
                                             float* __restrict__ outp) {
    int warp = (blockIdx.x * 256 + threadIdx.x) >> 5;
    int lane = threadIdx.x & 31;
    if (warp >= NN) return;
    const int n = warp;
    const int base = g_rowptr[n];
    const int deg = g_rowptr[n + 1] - base;
    const float2 erd = g_er[n];

    const int h = lane >> 4;
    const float erh = h ? erd.y : erd.x;
    float den = 0.f;
    float4 acc = make_float4(0.f, 0.f, 0.f, 0.f);
    const float4* zp = (const float4*)g_z;

    int j = 0;
    for (; j + 4 <= deg; j += 4) {
        int s0 = g_csrc[base + j];
        int s1 = g_csrc[base + j + 1];
        int s2 = g_csrc[base + j + 2];
        int s3 = g_csrc[base + j + 3];
        float2 a0 = g_el[s0];
        float2 a1 = g_el[s1];
        float2 a2 = g_el[s2];
        float2 a3 = g_el[s3];
        float4 v0 = zp[s0 * 32 + lane];
        float4 v1 = zp[s1 * 32 + lane];
        float4 v2 = zp[s2 * 32 + lane];
        float4 v3 = zp[s3 * 32 + lane];
        float w0 = __expf(lrelu((h ? a0.y : a0.x) + erh));
        float w1 = __expf(lrelu((h ? a1.y : a1.x) + erh));
        float w2 = __expf(lrelu((h ? a2.y : a2.x) + erh));
        float w3 = __expf(lrelu((h ? a3.y : a3.x) + erh));
        den += (w0 + w1) + (w2 + w3);
        acc.x = fmaf(w0, v0.x, acc.x); acc.y = fmaf(w0, v0.y, acc.y);
        acc.z = fmaf(w0, v0.z, acc.z); acc.w = fmaf(w0, v0.w, acc.w);
        acc.x = fmaf(w1, v1.x, acc.x); acc.y = fmaf(w1, v1.y, acc.y);
        acc.z = fmaf(w1, v1.z, acc.z); acc.w = fmaf(w1, v1.w, acc.w);
        acc.x = fmaf(w2, v2.x, acc.x); acc.y = fmaf(w2, v2.y, acc.y);
        acc.z = fmaf(w2, v2.z, acc.z); acc.w = fmaf(w2, v2.w, acc.w);
        acc.x = fmaf(w3, v3.x, acc.x); acc.y = fmaf(w3, v3.y, acc.y);
        acc.z = fmaf(w3, v3.z, acc.z); acc.w = fmaf(w3, v3.w, acc.w);
    }
    for (; j < deg; j++) {
        int s = g_csrc[base + j];
        float2 a = g_el[s];
        float4 v = zp[s * 32 + lane];
        float w = __expf(lrelu((h ? a.y : a.x) + erh));
        den += w;
        acc.x = fmaf(w, v.x, acc.x); acc.y = fmaf(w, v.y, acc.y);
        acc.z = fmaf(w, v.z, acc.z); acc.w = fmaf(w, v.w, acc.w);
    }

    const float inv = (deg > 0) ? 1.f / den : 0.f;
    acc.x *= inv; acc.y *= inv; acc.z *= inv; acc.w *= inv;

    // head mean across lane pairs (lane ^ 16)
    float ox = 0.5f * (acc.x + __shfl_xor_sync(0xffffffffu, acc.x, 16));
    float oy = 0.5f * (acc.y + __shfl_xor_sync(0xffffffffu, acc.y, 16));
    float oz = 0.5f * (acc.z + __shfl_xor_sync(0xffffffffu, acc.z, 16));
    float ow = 0.5f * (acc.w + __shfl_xor_sync(0xffffffffu, acc.w, 16));
    const int q = lane & 15;
    float4 bl = ((const float4*)bias)[q];
    float4 bh = ((const float4*)bias)[q + 16];
    ox += 0.5f * (bl.x + bh.x);
    oy += 0.5f * (bl.y + bh.y);
    oz += 0.5f * (bl.z + bh.z);
    ow += 0.5f * (bl.w + bh.w);

    if (LAYER == 1) {
        float lsum = ox + oy + oz + ow;
        float lsq = ox * ox + oy * oy + oz * oz + ow * ow;
#pragma unroll
        for (int o = 16; o; o >>= 1) {
            lsum += __shfl_xor_sync(0xffffffffu, lsum, o);
            lsq  += __shfl_xor_sync(0xffffffffu, lsq, o);
        }
        float mu = lsum * (1.f / 128.f);
        float var = lsq * (1.f / 128.f) - mu * mu;
        float rs = rsqrtf(var + LN_EPS);
        if (lane < 16) {
            float4 g = ((const float4*)gamma)[q];
            float4 be = ((const float4*)beta)[q];
            float y0 = fmaxf((ox - mu) * rs * g.x + be.x, 0.f);
            float y1 = fmaxf((oy - mu) * rs * g.y + be.y, 0.f);
            float y2 = fmaxf((oz - mu) * rs * g.z + be.z, 0.f);
            float y3 = fmaxf((ow - mu) * rs * g.w + be.w, 0.f);
            ((float4*)outp)[n * 16 + q] = make_float4(y0, y1, y2, y3);
        }
    } else {
        if (lane < 16) ((float4*)outp)[n * 16 + q] = make_float4(ox, oy, oz, ow);
    }
}

// ---------------- host ----------------
extern "C" void kernel_launch(void* const* d_in, const int* in_sizes, int n_in,
                              void* d_out, int out_size) {
    const float* feat   = (const float*)d_in[0];
    const int*   src    = (const int*)d_in[1];
    const int*   dst    = (const int*)d_in[2];
    const float* W1     = (const float*)d_in[3];
    const float* al1    = (const float*)d_in[4];
    const float* ar1    = (const float*)d_in[5];
    const float* b1     = (const float*)d_in[6];
    const float* gamma1 = (const float*)d_in[7];
    const float* beta1  = (const float*)d_in[8];
    const float* W2     = (const float*)d_in[9];
    const float* al2    = (const float*)d_in[10];
    const float* ar2    = (const float*)d_in[11];
    const float* b2     = (const float*)d_in[12];
    float* out = (float*)d_out;
    (void)in_sizes; (void)n_in; (void)out_size;

    void* tmp;
    cudaGetSymbolAddress(&tmp, g_cnt);  int* cntp = (int*)tmp;
    cudaGetSymbolAddress(&tmp, g_h1);   float* h1p = (float*)tmp;

    const int smem_bytes = (8192 + 128 * 68 + 256) * (int)sizeof(float);  // 68608
    cudaFuncSetAttribute((const void*)gemm_k<128>,
                         cudaFuncAttributeMaxDynamicSharedMemorySize, smem_bytes);
    cudaFuncSetAttribute((const void*)gemm_k<64>,
                         cudaFuncAttributeMaxDynamicSharedMemorySize, smem_bytes);

    const int ngrid = (NN + 127) / 128;

    // gemm1 kept as overall launch #6 so ncu -s5 -c1 lands on it again.
    cudaMemsetAsync(cntp, 0, NN * sizeof(int));
    hist_k<<<(NE + 255) / 256, 256>>>(dst);
    scan_blk_k<<<(NN + 1023) / 1024, 256>>>();
    scan_top_k<<<1, 128>>>((NN + 1023) / 1024);
    gemm_k<128><<<ngrid, 256, smem_bytes>>>(feat, W1, al1, ar1);
    scan_add_k<<<(NN + 255) / 256, 256>>>();
    cudaMemsetAsync(cntp, 0, NN * sizeof(int));
    scatter_k<<<(NE + 255) / 256, 256>>>(src, dst);

    agg_k<1><<<(NN + 7) / 8, 256>>>(b1, gamma1, beta1, h1p);
    gemm_k<64><<<ngrid, 256, smem_bytes>>>(h1p, W2, al2, ar2);
    agg_k<2><<<(NN + 7) / 8, 256>>>(b2, nullptr, nullptr, out);
}

// round 10
// speedup vs baseline: 1.0093x; 1.0093x over previous
#include <cuda_runtime.h>
#include <cstdint>

#define NN 100000
#define NE 800000
#define SLOPE 0.2f
#define LN_EPS 1e-5f

typedef unsigned long long ull;

// ---------------- scratch (static device globals; no allocation) ----------------
__device__ float  g_z[NN * 128];      // GEMM output z [N,2,64]
__device__ float2 g_el[NN];
__device__ float2 g_er[NN];
__device__ float  g_h1[NN * 64];
__device__ int    g_rowptr[NN + 1];
__device__ int    g_cnt[NN];
__device__ int    g_csrc[NE];
__device__ int    g_blksum[128];

// ---------------- f32x2 packed helpers ----------------
__device__ __forceinline__ void ffma2(ull& d, ull a, ull b) {
    asm("fma.rn.f32x2 %0, %1, %2, %0;" : "+l"(d) : "l"(a), "l"(b));
}
__device__ __forceinline__ float2 unpk(ull v) {
    uint32_t lo, hi;
    asm("mov.b64 {%0, %1}, %2;" : "=r"(lo), "=r"(hi) : "l"(v));
    return make_float2(__uint_as_float(lo), __uint_as_float(hi));
}

// ---------------- CSR build ----------------
__global__ void hist_k(const int* __restrict__ dst) {
    int i = blockIdx.x * 256 + threadIdx.x;
    if (i < NE) atomicAdd(&g_cnt[dst[i]], 1);
}

__global__ void scan_blk_k() {
    __shared__ int sh[256];
    int t = threadIdx.x, b = blockIdx.x;
    int base = b * 1024 + t * 4;
    int v0 = 0, v1 = 0, v2 = 0, v3 = 0;
    if (base + 0 < NN) v0 = g_cnt[base + 0];
    if (base + 1 < NN) v1 = g_cnt[base + 1];
    if (base + 2 < NN) v2 = g_cnt[base + 2];
    if (base + 3 < NN) v3 = g_cnt[base + 3];
    int tsum = v0 + v1 + v2 + v3;
    sh[t] = tsum;
    __syncthreads();
    for (int off = 1; off < 256; off <<= 1) {
        int x = 0;
        if (t >= off) x = sh[t - off];
        __syncthreads();
        sh[t] += x;
        __syncthreads();
    }
    int excl = sh[t] - tsum;
    if (t == 255) g_blksum[b] = sh[255];
    if (base + 0 < NN) g_rowptr[base + 0] = excl;
    if (base + 1 < NN) g_rowptr[base + 1] = excl + v0;
    if (base + 2 < NN) g_rowptr[base + 2] = excl + v0 + v1;
    if (base + 3 < NN) g_rowptr[base + 3] = excl + v0 + v1 + v2;
}

__global__ void scan_top_k(int g) {
    __shared__ int sh[128];
    int t = threadIdx.x;
    int v = (t < g) ? g_blksum[t] : 0;
    sh[t] = v;
    __syncthreads();
    for (int off = 1; off < 128; off <<= 1) {
        int x = 0;
        if (t >= off) x = sh[t - off];
        __syncthreads();
        sh[t] += x;
        __syncthreads();
    }
    if (t < g) g_blksum[t] = sh[t] - v;
}

__global__ void scan_add_k() {
    int i = blockIdx.x * 256 + threadIdx.x;
    if (i < NN) g_rowptr[i] += g_blksum[i >> 10];
    if (i == 0) g_rowptr[NN] = NE;
}

__global__ void scatter_k(const int* __restrict__ src, const int* __restrict__ dst) {
    int i = blockIdx.x * 256 + threadIdx.x;
    if (i < NE) {
        int d = dst[i];
        int p = g_rowptr[d] + atomicAdd(&g_cnt[d], 1);
        g_csrc[p] = src[i];
    }
}

// ---------------- GEMM: z = x @ W, 512 threads, 4x8 thread tile, dup-X smem ----------------
// Block 512 = 16(tx) x 32(ty). Thread: rows ty*4..ty*4+3, cols {tx*4.., 64+tx*4..}.
// X stored duplicated (each value as an 8B pair) -> LDS.64 feeds FFMA2 directly, no MOVs.
// Per kk: 2 LDS.128 (W) + 4 LDS.64 (X) + 16 FFMA2 = 22 issue slots.
// __launch_bounds__(512,2): 2 CTAs/SM (32 warps, 50% occ) to hide LDS latency and
// overlap tile-load phases across CTAs.
template <int FIN>
__global__ void __launch_bounds__(512, 2) gemm_k(const float* __restrict__ x,
                                                 const float* __restrict__ W,
                                                 const float* __restrict__ al,
                                                 const float* __restrict__ ar) {
    extern __shared__ float sm[];
    float* Ws  = sm;                     // 64*128 = 8192 floats
    float* Xd  = sm + 8192;              // 128 rows * 132 floats (64 dup pairs + pad)
    float* Als = sm + 8192 + 128 * 132;  // 128
    float* Ars = Als + 128;              // 128

    const int tid = threadIdx.x;
    if (tid < 128) { Als[tid] = al[tid]; Ars[tid] = ar[tid]; }

    const int tx = tid & 15, ty = tid >> 4;
    const int n0 = blockIdx.x * 128;

    ull acc[4][4];
#pragma unroll
    for (int j = 0; j < 4; j++)
#pragma unroll
        for (int c = 0; c < 4; c++) acc[j][c] = 0ull;

    for (int kt = 0; kt < FIN; kt += 64) {
        // W tile: 64 rows x 128 cols (contiguous)
        const float4* Wg = (const float4*)(W + kt * 128);
        float4* Wsv = (float4*)Ws;
#pragma unroll
        for (int i = tid; i < 2048; i += 512) Wsv[i] = Wg[i];
        // X tile: 128 rows x 64 cols -> duplicated pairs, stride 132 floats
#pragma unroll
        for (int i = tid; i < 2048; i += 512) {
            int r = i >> 4, c4 = i & 15;
            int gr = n0 + r;
            float4 v = make_float4(0.f, 0.f, 0.f, 0.f);
            if (gr < NN) v = *(const float4*)(x + gr * FIN + kt + c4 * 4);
            float* p = Xd + r * 132 + c4 * 8;
            *(float4*)(p + 0) = make_float4(v.x, v.x, v.y, v.y);
            *(float4*)(p + 4) = make_float4(v.z, v.z, v.w, v.w);
        }
        __syncthreads();
#pragma unroll 8
        for (int kk = 0; kk < 64; kk++) {
            ulonglong2 wA = *(const ulonglong2*)(Ws + kk * 128 + tx * 4);
            ulonglong2 wB = *(const ulonglong2*)(Ws + kk * 128 + 64 + tx * 4);
#pragma unroll
            for (int j = 0; j < 4; j++) {
                ull xx = *(const ull*)(Xd + (ty * 4 + j) * 132 + kk * 2);
                ffma2(acc[j][0], xx, wA.x);
                ffma2(acc[j][1], xx, wA.y);
                ffma2(acc[j][2], xx, wB.x);
                ffma2(acc[j][3], xx, wB.y);
            }
        }
        __syncthreads();
    }

    // epilogue: per-row el/er partial dots + 16-lane butterfly over tx; store z
    const float* al0 = Als + tx * 4;
    const float* ar0 = Ars + tx * 4;
    const float* al1 = Als + 64 + tx * 4;
    const float* ar1 = Ars + 64 + tx * 4;
#pragma unroll
    for (int j = 0; j < 4; j++) {
        int r = ty * 4 + j;
        float2 c0 = unpk(acc[j][0]), c1 = unpk(acc[j][1]);
        float2 c2 = unpk(acc[j][2]), c3 = unpk(acc[j][3]);
        float el0 = c0.x * al0[0] + c0.y * al0[1] + c1.x * al0[2] + c1.y * al0[3];
        float er0 = c0.x * ar0[0] + c0.y * ar0[1] + c1.x * ar0[2] + c1.y * ar0[3];
        float el1 = c2.x * al1[0] + c2.y * al1[1] + c3.x * al1[2] + c3.y * al1[3];
        float er1 = c2.x * ar1[0] + c2.y * ar1[1] + c3.x * ar1[2] + c3.y * ar1[3];
#pragma unroll
        for (int o = 1; o <= 8; o <<= 1) {
            el0 += __shfl_xor_sync(0xffffffffu, el0, o);
            er0 += __shfl_xor_sync(0xffffffffu, er0, o);
            el1 += __shfl_xor_sync(0xffffffffu, el1, o);
            er1 += __shfl_xor_sync(0xffffffffu, er1, o);
        }
        int gr = n0 + r;
        if (gr < NN) {
            ulonglong2 v0, v1;
            v0.x = acc[j][0]; v0.y = acc[j][1];
            v1.x = acc[j][2]; v1.y = acc[j][3];
            *(ulonglong2*)(g_z + gr * 128 + tx * 4) = v0;
            *(ulonglong2*)(g_z + gr * 128 + 64 + tx * 4) = v1;
            if (tx == 0) {
                g_el[gr] = make_float2(el0, el1);
                g_er[gr] = make_float2(er0, er1);
            }
        }
    }
}

// ---------------- warp-per-node: SINGLE-PASS edge softmax + aggregate (unroll 4) ----------------
__device__ __forceinline__ float lrelu(float v) { return v > 0.f ? v : SLOPE * v; }

template <int LAYER>
__global__ void __launch_bounds__(256) agg_k(const float* __restrict__ bias,
                                             const float* __restrict__ gamma,
                                             const float* __restrict__ beta,
                                             float* __restrict__ outp) {
    int warp = (blockIdx.x * 256 + threadIdx.x) >> 5;
    int lane = threadIdx.x & 31;
    if (warp >= NN) return;
    const int n = warp;
    const int base = g_rowptr[n];
    const int deg = g_rowptr[n + 1] - base;
    const float2 erd = g_er[n];

    const int h = lane >> 4;
    const float erh = h ? erd.y : erd.x;
    float den = 0.f;
    float4 acc = make_float4(0.f, 0.f, 0.f, 0.f);
    const float4* zp = (const float4*)g_z;

    int j = 0;
    for (; j + 4 <= deg; j += 4) {
        int s0 = g_csrc[base + j];
        int s1 = g_csrc[base + j + 1];
        int s2 = g_csrc[base + j + 2];
        int s3 = g_csrc[base + j + 3];
        float2 a0 = g_el[s0];
        float2 a1 = g_el[s1];
        float2 a2 = g_el[s2];
        float2 a3 = g_el[s3];
        float4 v0 = zp[s0 * 32 + lane];
        float4 v1 = zp[s1 * 32 + lane];
        float4 v2 = zp[s2 * 32 + lane];
        float4 v3 = zp[s3 * 32 + lane];
        float w0 = __expf(lrelu((h ? a0.y : a0.x) + erh));
        float w1 = __expf(lrelu((h ? a1.y : a1.x) + erh));
        float w2 = __expf(lrelu((h ? a2.y : a2.x) + erh));
        float w3 = __expf(lrelu((h ? a3.y : a3.x) + erh));
        den += (w0 + w1) + (w2 + w3);
        acc.x = fmaf(w0, v0.x, acc.x); acc.y = fmaf(w0, v0.y, acc.y);
        acc.z = fmaf(w0, v0.z, acc.z); acc.w = fmaf(w0, v0.w, acc.w);
        acc.x = fmaf(w1, v1.x, acc.x); acc.y = fmaf(w1, v1.y, acc.y);
        acc.z = fmaf(w1, v1.z, acc.z); acc.w = fmaf(w1, v1.w, acc.w);
        acc.x = fmaf(w2, v2.x, acc.x); acc.y = fmaf(w2, v2.y, acc.y);
        acc.z = fmaf(w2, v2.z, acc.z); acc.w = fmaf(w2, v2.w, acc.w);
        acc.x = fmaf(w3, v3.x, acc.x); acc.y = fmaf(w3, v3.y, acc.y);
        acc.z = fmaf(w3, v3.z, acc.z); acc.w = fmaf(w3, v3.w, acc.w);
    }
    for (; j < deg; j++) {
        int s = g_csrc[base + j];
        float2 a = g_el[s];
        float4 v = zp[s * 32 + lane];
        float w = __expf(lrelu((h ? a.y : a.x) + erh));
        den += w;
        acc.x = fmaf(w, v.x, acc.x); acc.y = fmaf(w, v.y, acc.y);
        acc.z = fmaf(w, v.z, acc.z); acc.w = fmaf(w, v.w, acc.w);
    }

    const float inv = (deg > 0) ? 1.f / den : 0.f;
    acc.x *= inv; acc.y *= inv; acc.z *= inv; acc.w *= inv;

    // head mean across lane pairs (lane ^ 16)
    float ox = 0.5f * (acc.x + __shfl_xor_sync(0xffffffffu, acc.x, 16));
    float oy = 0.5f * (acc.y + __shfl_xor_sync(0xffffffffu, acc.y, 16));
    float oz = 0.5f * (acc.z + __shfl_xor_sync(0xffffffffu, acc.z, 16));
    float ow = 0.5f * (acc.w + __shfl_xor_sync(0xffffffffu, acc.w, 16));
    const int q = lane & 15;
    float4 bl = ((const float4*)bias)[q];
    float4 bh = ((const float4*)bias)[q + 16];
    ox += 0.5f * (bl.x + bh.x);
    oy += 0.5f * (bl.y + bh.y);
    oz += 0.5f * (bl.z + bh.z);
    ow += 0.5f * (bl.w + bh.w);

    if (LAYER == 1) {
        float lsum = ox + oy + oz + ow;
        float lsq = ox * ox + oy * oy + oz * oz + ow * ow;
#pragma unroll
        for (int o = 16; o; o >>= 1) {
            lsum += __shfl_xor_sync(0xffffffffu, lsum, o);
            lsq  += __shfl_xor_sync(0xffffffffu, lsq, o);
        }
        float mu = lsum * (1.f / 128.f);
        float var = lsq * (1.f / 128.f) - mu * mu;
        float rs = rsqrtf(var + LN_EPS);
        if (lane < 16) {
            float4 g = ((const float4*)gamma)[q];
            float4 be = ((const float4*)beta)[q];
            float y0 = fmaxf((ox - mu) * rs * g.x + be.x, 0.f);
            float y1 = fmaxf((oy - mu) * rs * g.y + be.y, 0.f);
            float y2 = fmaxf((oz - mu) * rs * g.z + be.z, 0.f);
            float y3 = fmaxf((ow - mu) * rs * g.w + be.w, 0.f);
            ((float4*)outp)[n * 16 + q] = make_float4(y0, y1, y2, y3);
        }
    } else {
        if (lane < 16) ((float4*)outp)[n * 16 + q] = make_float4(ox, oy, oz, ow);
    }
}

// ---------------- host ----------------
extern "C" void kernel_launch(void* const* d_in, const int* in_sizes, int n_in,
                              void* d_out, int out_size) {
    const float* feat   = (const float*)d_in[0];
    const int*   src    = (const int*)d_in[1];
    const int*   dst    = (const int*)d_in[2];
    const float* W1     = (const float*)d_in[3];
    const float* al1    = (const float*)d_in[4];
    const float* ar1    = (const float*)d_in[5];
    const float* b1     = (const float*)d_in[6];
    const float* gamma1 = (const float*)d_in[7];
    const float* beta1  = (const float*)d_in[8];
    const float* W2     = (const float*)d_in[9];
    const float* al2    = (const float*)d_in[10];
    const float* ar2    = (const float*)d_in[11];
    const float* b2     = (const float*)d_in[12];
    float* out = (float*)d_out;
    (void)in_sizes; (void)n_in; (void)out_size;

    void* tmp;
    cudaGetSymbolAddress(&tmp, g_cnt);  int* cntp = (int*)tmp;
    cudaGetSymbolAddress(&tmp, g_h1);   float* h1p = (float*)tmp;

    // Ws 8192 + Xd 128*132 + Als/Ars 256 floats = 25344 floats = 101376 B
    const int smem_bytes = (8192 + 128 * 132 + 256) * (int)sizeof(float);
    cudaFuncSetAttribute((const void*)gemm_k<128>,
                         cudaFuncAttributeMaxDynamicSharedMemorySize, smem_bytes);
    cudaFuncSetAttribute((const void*)gemm_k<64>,
                         cudaFuncAttributeMaxDynamicSharedMemorySize, smem_bytes);

    const int ngrid = (NN + 127) / 128;

    // gemm1 kept as overall launch #6 so ncu -s5 -c1 lands on it again.
    cudaMemsetAsync(cntp, 0, NN * sizeof(int));
    hist_k<<<(NE + 255) / 256, 256>>>(dst);
    scan_blk_k<<<(NN + 1023) / 1024, 256>>>();
    scan_top_k<<<1, 128>>>((NN + 1023) / 1024);
    gemm_k<128><<<ngrid, 512, smem_bytes>>>(feat, W1, al1, ar1);
    scan_add_k<<<(NN + 255) / 256, 256>>>();
    cudaMemsetAsync(cntp, 0, NN * sizeof(int));
    scatter_k<<<(NE + 255) / 256, 256>>>(src, dst);

    agg_k<1><<<(NN + 7) / 8, 256>>>(b1, gamma1, beta1, h1p);
    gemm_k<64><<<ngrid, 512, smem_bytes>>>(h1p, W2, al2, ar2);
    agg_k<2><<<(NN + 7) / 8, 256>>>(b2, nullptr, nullptr, out);
}

// round 12
// speedup vs baseline: 1.2099x; 1.1987x over previous
#include <cuda_runtime.h>
#include <cuda_fp16.h>
#include <cstdint>

#define NN 100000
#define NE 800000
#define SLOPE 0.2f
#define LN_EPS 1e-5f

typedef unsigned long long ull;

// ---------------- scratch (static device globals; no allocation) ----------------
__device__ __half g_zh[NN * 128];     // GEMM output z [N,2,64] in fp16 (256 B/row)
__device__ float2 g_el[NN];
__device__ float2 g_er[NN];
__device__ float  g_h1[NN * 64];
__device__ int    g_rowptr[NN + 1];
__device__ int    g_cnt[NN];
__device__ int    g_csrc[NE];
__device__ int    g_blksum[128];

// ---------------- f32x2 packed helpers ----------------
__device__ __forceinline__ void ffma2(ull& d, ull a, ull b) {
    asm("fma.rn.f32x2 %0, %1, %2, %0;" : "+l"(d) : "l"(a), "l"(b));
}
__device__ __forceinline__ ull bcast2(float x) {
    ull r;
    uint32_t u = __float_as_uint(x);
    asm("mov.b64 %0, {%1, %1};" : "=l"(r) : "r"(u));
    return r;
}
__device__ __forceinline__ float2 unpk(ull v) {
    uint32_t lo, hi;
    asm("mov.b64 {%0, %1}, %2;" : "=r"(lo), "=r"(hi) : "l"(v));
    return make_float2(__uint_as_float(lo), __uint_as_float(hi));
}

// ---------------- CSR build ----------------
__global__ void hist_k(const int* __restrict__ dst) {
    int i = blockIdx.x * 256 + threadIdx.x;
    if (i < NE) atomicAdd(&g_cnt[dst[i]], 1);
}

__global__ void scan_blk_k() {
    __shared__ int sh[256];
    int t = threadIdx.x, b = blockIdx.x;
    int base = b * 1024 + t * 4;
    int v0 = 0, v1 = 0, v2 = 0, v3 = 0;
    if (base + 0 < NN) v0 = g_cnt[base + 0];
    if (base + 1 < NN) v1 = g_cnt[base + 1];
    if (base + 2 < NN) v2 = g_cnt[base + 2];
    if (base + 3 < NN) v3 = g_cnt[base + 3];
    int tsum = v0 + v1 + v2 + v3;
    sh[t] = tsum;
    __syncthreads();
    for (int off = 1; off < 256; off <<= 1) {
        int x = 0;
        if (t >= off) x = sh[t - off];
        __syncthreads();
        sh[t] += x;
        __syncthreads();
    }
    int excl = sh[t] - tsum;
    if (t == 255) g_blksum[b] = sh[255];
    if (base + 0 < NN) g_rowptr[base + 0] = excl;
    if (base + 1 < NN) g_rowptr[base + 1] = excl + v0;
    if (base + 2 < NN) g_rowptr[base + 2] = excl + v0 + v1;
    if (base + 3 < NN) g_rowptr[base + 3] = excl + v0 + v1 + v2;
}

__global__ void scan_top_k(int g) {
    __shared__ int sh[128];
    int t = threadIdx.x;
    int v = (t < g) ? g_blksum[t] : 0;
    sh[t] = v;
    __syncthreads();
    for (int off = 1; off < 128; off <<= 1) {
        int x = 0;
        if (t >= off) x = sh[t - off];
        __syncthreads();
        sh[t] += x;
        __syncthreads();
    }
    if (t < g) g_blksum[t] = sh[t] - v;
}

__global__ void scan_add_k() {
    int i = blockIdx.x * 256 + threadIdx.x;
    if (i < NN) g_rowptr[i] += g_blksum[i >> 10];
    if (i == 0) g_rowptr[NN] = NE;
}

__global__ void scatter_k(const int* __restrict__ src, const int* __restrict__ dst) {
    int i = blockIdx.x * 256 + threadIdx.x;
    if (i < NE) {
        int d = dst[i];
        int p = g_rowptr[d] + atomicAdd(&g_cnt[d], 1);
        g_csrc[p] = src[i];
    }
}

// ---------------- GEMM: z = x @ W, 8x8 register tile (R6 config), fp16 z store ----------------
// Block 256 = 16(tx) x 16(ty). Thread: rows {ty*4+j, 64+ty*4+j}, cols {tx*4.., 64+tx*4..}.
template <int FIN>
__global__ void __launch_bounds__(256) gemm_k(const float* __restrict__ x,
                                              const float* __restrict__ W,
                                              const float* __restrict__ al,
                                              const float* __restrict__ ar) {
    extern __shared__ float sm[];
    float* Ws  = sm;                    // 64*128
    float* Xs  = sm + 8192;             // 128*68 (padded stride 68)
    float* Als = sm + 8192 + 128 * 68;  // 128
    float* Ars = Als + 128;             // 128

    const int tid = threadIdx.x;
    if (tid < 128) { Als[tid] = al[tid]; Ars[tid] = ar[tid]; }

    const int tx = tid & 15, ty = tid >> 4;
    const int n0 = blockIdx.x * 128;

    ull acc[8][4];
#pragma unroll
    for (int j = 0; j < 8; j++)
#pragma unroll
        for (int c = 0; c < 4; c++) acc[j][c] = 0ull;

    for (int kt = 0; kt < FIN; kt += 64) {
        const float4* Wg = (const float4*)(W + kt * 128);
        float4* Wsv = (float4*)Ws;
        for (int i = tid; i < 2048; i += 256) Wsv[i] = Wg[i];
        for (int i = tid; i < 2048; i += 256) {
            int r = i >> 4, c4 = i & 15;
            int gr = n0 + r;
            float4 v = make_float4(0.f, 0.f, 0.f, 0.f);
            if (gr < NN) v = *(const float4*)(x + gr * FIN + kt + c4 * 4);
            *(float4*)(Xs + r * 68 + c4 * 4) = v;
        }
        __syncthreads();
#pragma unroll 4
        for (int kk = 0; kk < 64; kk++) {
            ulonglong2 wA = *(const ulonglong2*)(Ws + kk * 128 + tx * 4);
            ulonglong2 wB = *(const ulonglong2*)(Ws + kk * 128 + 64 + tx * 4);
            float xr[8];
#pragma unroll
            for (int j = 0; j < 4; j++) {
                xr[j]     = Xs[(ty * 4 + j) * 68 + kk];
                xr[4 + j] = Xs[(64 + ty * 4 + j) * 68 + kk];
            }
#pragma unroll
            for (int j = 0; j < 8; j++) {
                ull bx = bcast2(xr[j]);
                ffma2(acc[j][0], bx, wA.x);
                ffma2(acc[j][1], bx, wA.y);
                ffma2(acc[j][2], bx, wB.x);
                ffma2(acc[j][3], bx, wB.y);
            }
        }
        __syncthreads();
    }

    // epilogue: el/er partial dots (fp32) + 16-lane butterfly; store z as fp16
    const float* al0 = Als + tx * 4;
    const float* ar0 = Ars + tx * 4;
    const float* al1 = Als + 64 + tx * 4;
    const float* ar1 = Ars + 64 + tx * 4;
#pragma unroll
    for (int j = 0; j < 8; j++) {
        int r = (j < 4) ? (ty * 4 + j) : (64 + ty * 4 + (j - 4));
        float2 c0 = unpk(acc[j][0]), c1 = unpk(acc[j][1]);
        float2 c2 = unpk(acc[j][2]), c3 = unpk(acc[j][3]);
        float el0 = c0.x * al0[0] + c0.y * al0[1] + c1.x * al0[2] + c1.y * al0[3];
        float er0 = c0.x * ar0[0] + c0.y * ar0[1] + c1.x * ar0[2] + c1.y * ar0[3];
        float el1 = c2.x * al1[0] + c2.y * al1[1] + c3.x * al1[2] + c3.y * al1[3];
        float er1 = c2.x * ar1[0] + c2.y * ar1[1] + c3.x * ar1[2] + c3.y * ar1[3];
#pragma unroll
        for (int o = 1; o <= 8; o <<= 1) {
            el0 += __shfl_xor_sync(0xffffffffu, el0, o);
            er0 += __shfl_xor_sync(0xffffffffu, er0, o);
            el1 += __shfl_xor_sync(0xffffffffu, el1, o);
            er1 += __shfl_xor_sync(0xffffffffu, er1, o);
        }
        int gr = n0 + r;
        if (gr < NN) {
            __half2 h01 = __floats2half2_rn(c0.x, c0.y);
            __half2 h23 = __floats2half2_rn(c1.x, c1.y);
            __half2 h45 = __floats2half2_rn(c2.x, c2.y);
            __half2 h67 = __floats2half2_rn(c3.x, c3.y);
            uint2 v0, v1;
            v0.x = *(uint32_t*)&h01; v0.y = *(uint32_t*)&h23;
            v1.x = *(uint32_t*)&h45; v1.y = *(uint32_t*)&h67;
            *(uint2*)(g_zh + gr * 128 + tx * 4) = v0;
            *(uint2*)(g_zh + gr * 128 + 64 + tx * 4) = v1;
            if (tx == 0) {
                g_el[gr] = make_float2(el0, el1);
                g_er[gr] = make_float2(er0, er1);
            }
        }
    }
}

// ---------------- warp-per-node: single-pass softmax + aggregate (fp16 z, unroll 4) ----------------
__device__ __forceinline__ float lrelu(float v) { return v > 0.f ? v : SLOPE * v; }

__device__ __forceinline__ float4 h4_to_f4(uint2 u) {
    float2 lo = __half22float2(*(__half2*)&u.x);
    float2 hi = __half22float2(*(__half2*)&u.y);
    return make_float4(lo.x, lo.y, hi.x, hi.y);
}

template <int LAYER>
__global__ void __launch_bounds__(256) agg_k(const float* __restrict__ bias,
                                             const float* __restrict__ gamma,
                                             const float* __restrict__ beta,
                                             float* __restrict__ outp) {
    int warp = (blockIdx.x * 256 + threadIdx.x) >> 5;
    int lane = threadIdx.x & 31;
    if (warp >= NN) return;
    const int n = warp;
    const int base = g_rowptr[n];
    const int deg = g_rowptr[n + 1] - base;
    const float2 erd = g_er[n];

    const int h = lane >> 4;
    const float erh = h ? erd.y : erd.x;
    float den = 0.f;
    float4 acc = make_float4(0.f, 0.f, 0.f, 0.f);
    const uint2* zp = (const uint2*)g_zh;  // 4 halves per uint2; row = 32 uint2

    int j = 0;
    for (; j + 4 <= deg; j += 4) {
        int s0 = g_csrc[base + j];
        int s1 = g_csrc[base + j + 1];
        int s2 = g_csrc[base + j + 2];
        int s3 = g_csrc[base + j + 3];
        float2 a0 = g_el[s0];
        float2 a1 = g_el[s1];
        float2 a2 = g_el[s2];
        float2 a3 = g_el[s3];
        uint2 u0 = zp[s0 * 32 + lane];
        uint2 u1 = zp[s1 * 32 + lane];
        uint2 u2 = zp[s2 * 32 + lane];
        uint2 u3 = zp[s3 * 32 + lane];
        float w0 = __expf(lrelu((h ? a0.y : a0.x) + erh));
        float w1 = __expf(lrelu((h ? a1.y : a1.x) + erh));
        float w2 = __expf(lrelu((h ? a2.y : a2.x) + erh));
        float w3 = __expf(lrelu((h ? a3.y : a3.x) + erh));
        den += (w0 + w1) + (w2 + w3);
        float4 v0 = h4_to_f4(u0), v1 = h4_to_f4(u1), v2 = h4_to_f4(u2), v3 = h4_to_f4(u3);
        acc.x = fmaf(w0, v0.x, acc.x); acc.y = fmaf(w0, v0.y, acc.y);
        acc.z = fmaf(w0, v0.z, acc.z); acc.w = fmaf(w0, v0.w, acc.w);
        acc.x = fmaf(w1, v1.x, acc.x); acc.y = fmaf(w1, v1.y, acc.y);
        acc.z = fmaf(w1, v1.z, acc.z); acc.w = fmaf(w1, v1.w, acc.w);
        acc.x = fmaf(w2, v2.x, acc.x); acc.y = fmaf(w2, v2.y, acc.y);
        acc.z = fmaf(w2, v2.z, acc.z); acc.w = fmaf(w2, v2.w, acc.w);
        acc.x = fmaf(w3, v3.x, acc.x); acc.y = fmaf(w3, v3.y, acc.y);
        acc.z = fmaf(w3, v3.z, acc.z); acc.w = fmaf(w3, v3.w, acc.w);
    }
    for (; j < deg; j++) {
        int s = g_csrc[base + j];
        float2 a = g_el[s];
        uint2 u = zp[s * 32 + lane];
        float w = __expf(lrelu((h ? a.y : a.x) + erh));
        den += w;
        float4 v = h4_to_f4(u);
        acc.x = fmaf(w, v.x, acc.x); acc.y = fmaf(w, v.y, acc.y);
        acc.z = fmaf(w, v.z, acc.z); acc.w = fmaf(w, v.w, acc.w);
    }

    const float inv = (deg > 0) ? 1.f / den : 0.f;
    acc.x *= inv; acc.y *= inv; acc.z *= inv; acc.w *= inv;

    // head mean across lane pairs (lane ^ 16)
    float ox = 0.5f * (acc.x + __shfl_xor_sync(0xffffffffu, acc.x, 16));
    float oy = 0.5f * (acc.y + __shfl_xor_sync(0xffffffffu, acc.y, 16));
    float oz = 0.5f * (acc.z + __shfl_xor_sync(0xffffffffu, acc.z, 16));
    float ow = 0.5f * (acc.w + __shfl_xor_sync(0xffffffffu, acc.w, 16));
    const int q = lane & 15;
    float4 bl = ((const float4*)bias)[q];
    float4 bh = ((const float4*)bias)[q + 16];
    ox += 0.5f * (bl.x + bh.x);
    oy += 0.5f * (bl.y + bh.y);
    oz += 0.5f * (bl.z + bh.z);
    ow += 0.5f * (bl.w + bh.w);

    if (LAYER == 1) {
        float lsum = ox + oy + oz + ow;
        float lsq = ox * ox + oy * oy + oz * oz + ow * ow;
#pragma unroll
        for (int o = 16; o; o >>= 1) {
            lsum += __shfl_xor_sync(0xffffffffu, lsum, o);
            lsq  += __shfl_xor_sync(0xffffffffu, lsq, o);
        }
        float mu = lsum * (1.f / 128.f);
        float var = lsq * (1.f / 128.f) - mu * mu;
        float rs = rsqrtf(var + LN_EPS);
        if (lane < 16) {
            float4 g = ((const float4*)gamma)[q];
            float4 be = ((const float4*)beta)[q];
            float y0 = fmaxf((ox - mu) * rs * g.x + be.x, 0.f);
            float y1 = fmaxf((oy - mu) * rs * g.y + be.y, 0.f);
            float y2 = fmaxf((oz - mu) * rs * g.z + be.z, 0.f);
            float y3 = fmaxf((ow - mu) * rs * g.w + be.w, 0.f);
            ((float4*)outp)[n * 16 + q] = make_float4(y0, y1, y2, y3);
        }
    } else {
        if (lane < 16) ((float4*)outp)[n * 16 + q] = make_float4(ox, oy, oz, ow);
    }
}

// ---------------- host ----------------
extern "C" void kernel_launch(void* const* d_in, const int* in_sizes, int n_in,
                              void* d_out, int out_size) {
    const float* feat   = (const float*)d_in[0];
    const int*   src    = (const int*)d_in[1];
    const int*   dst    = (const int*)d_in[2];
    const float* W1     = (const float*)d_in[3];
    const float* al1    = (const float*)d_in[4];
    const float* ar1    = (const float*)d_in[5];
    const float* b1     = (const float*)d_in[6];
    const float* gamma1 = (const float*)d_in[7];
    const float* beta1  = (const float*)d_in[8];
    const float* W2     = (const float*)d_in[9];
    const float* al2    = (const float*)d_in[10];
    const float* ar2    = (const float*)d_in[11];
    const float* b2     = (const float*)d_in[12];
    float* out = (float*)d_out;
    (void)in_sizes; (void)n_in; (void)out_size;

    void* tmp;
    cudaGetSymbolAddress(&tmp, g_cnt);  int* cntp = (int*)tmp;
    cudaGetSymbolAddress(&tmp, g_h1);   float* h1p = (float*)tmp;

    const int smem_bytes = (8192 + 128 * 68 + 256) * (int)sizeof(float);  // 68608
    cudaFuncSetAttribute((const void*)gemm_k<128>,
                         cudaFuncAttributeMaxDynamicSharedMemorySize, smem_bytes);
    cudaFuncSetAttribute((const void*)gemm_k<64>,
                         cudaFuncAttributeMaxDynamicSharedMemorySize, smem_bytes);

    const int ngrid = (NN + 127) / 128;

    // gemm1 kept as overall launch #6 so ncu -s5 -c1 lands on it again.
    cudaMemsetAsync(cntp, 0, NN * sizeof(int));
    hist_k<<<(NE + 255) / 256, 256>>>(dst);
    scan_blk_k<<<(NN + 1023) / 1024, 256>>>();
    scan_top_k<<<1, 128>>>((NN + 1023) / 1024);
    gemm_k<128><<<ngrid, 256, smem_bytes>>>(feat, W1, al1, ar1);
    scan_add_k<<<(NN + 255) / 256, 256>>>();
    cudaMemsetAsync(cntp, 0, NN * sizeof(int));
    scatter_k<<<(NE + 255) / 256, 256>>>(src, dst);

    agg_k<1><<<(NN + 7) / 8, 256>>>(b1, gamma1, beta1, h1p);
    gemm_k<64><<<ngrid, 256, smem_bytes>>>(h1p, W2, al2, ar2);
    agg_k<2><<<(NN + 7) / 8, 256>>>(b2, nullptr, nullptr, out);
}